// round 4
// baseline (speedup 1.0000x reference)
#include <cuda_runtime.h>
#include <math.h>
#include <stdint.h>

#define REF_Y 0.5f
#define EPSF  1e-08f

#define NBLK  8                 // cluster of 8 CTAs
#define NTHR  256               // 8 warps/CTA
#define NWARP (NTHR / 32)       // 8
#define NLEAD (NBLK * NWARP)    // 64 warp leaders cluster-wide

__device__ __forceinline__ uint32_t smem_u32(const void* p) {
    uint32_t a;
    asm("{ .reg .u64 t; cvta.to.shared.u64 t, %1; cvt.u32.u64 %0, t; }"
        : "=r"(a) : "l"(p));
    return a;
}

__global__ __launch_bounds__(NTHR, 1) __cluster_dims__(NBLK, 1, 1)
void lamse_kernel(const float* __restrict__ x,
                  const float* __restrict__ t,
                  float* __restrict__ out,
                  int n) {
    // landing zone in CTA 0's SMEM: 64 leader slots x 8 floats (5 used)
    __shared__ float    part[NLEAD][8];
    __shared__ uint64_t mbar;

    const int tid = threadIdx.x;
    const int wid = tid >> 5;
    const int lid = tid & 31;
    uint32_t rank;
    asm("mov.u32 %0, %%cluster_ctarank;" : "=r"(rank));

    const int n4     = n >> 2;
    const int stride = NBLK * NTHR;
    const int gt     = (int)rank * NTHR + tid;

    const float4* __restrict__ x4 = (const float4*)x;
    const float4* __restrict__ t4 = (const float4*)t;

    // ---- issue the (single, for n=8192) vector loads FIRST ----
    bool   have = gt < n4;
    float4 xv, tv;
    if (have) { xv = x4[gt]; tv = t4[gt]; }

    // ---- mbarrier init + cluster barrier, hidden under DRAM latency ----
    uint32_t mb_local = smem_u32(&mbar);
    if (rank == 0 && tid == 0) {
        asm volatile("mbarrier.init.shared::cta.b64 [%0], %1;"
                     :: "r"(mb_local), "r"(NLEAD) : "memory");
        asm volatile("fence.mbarrier_init.release.cluster;" ::: "memory");
    }
    asm volatile("barrier.cluster.arrive.aligned;" ::: "memory");
    asm volatile("barrier.cluster.wait.aligned;"   ::: "memory");

    // ---- per-thread accumulation (5 sums; inputs are NaN-free normals) ----
    float s_w = 0.f, s_e = 0.f, s_ew = 0.f, s_e2 = 0.f, s_e2w = 0.f;

    #define PROC(xj, tj) do {                                            \
        float _w = fabsf(REF_Y - (tj)) /                                 \
                   (fabsf(REF_Y) + fabsf(tj) + EPSF);                    \
        _w = fminf(fmaxf(_w, 0.1f), 2.0f);                               \
        float _e = (xj) - (tj);                                          \
        s_w  += _w;                                                      \
        s_e  += _e;                                                      \
        s_ew  = fmaf(_e, _w, s_ew);                                      \
        s_e2  = fmaf(_e, _e, s_e2);                                      \
        s_e2w = fmaf(_e * _e, _w, s_e2w);                                \
    } while (0)

    if (have) {
        PROC(xv.x, tv.x); PROC(xv.y, tv.y);
        PROC(xv.z, tv.z); PROC(xv.w, tv.w);
    }
    for (int i = gt + stride; i < n4; i += stride) {
        float4 a = x4[i], b = t4[i];
        PROC(a.x, b.x); PROC(a.y, b.y); PROC(a.z, b.z); PROC(a.w, b.w);
    }
    for (int i = (n4 << 2) + gt; i < n; i += stride) {
        float xj = x[i], tj = t[i];
        PROC(xj, tj);
    }
    #undef PROC

    // ---- warp shuffle reduce (5 sums) ----
    #pragma unroll
    for (int off = 16; off > 0; off >>= 1) {
        s_w   += __shfl_down_sync(0xffffffffu, s_w,   off);
        s_e   += __shfl_down_sync(0xffffffffu, s_e,   off);
        s_ew  += __shfl_down_sync(0xffffffffu, s_ew,  off);
        s_e2  += __shfl_down_sync(0xffffffffu, s_e2,  off);
        s_e2w += __shfl_down_sync(0xffffffffu, s_e2w, off);
    }

    // ---- each warp leader DSMEM-stores its partials to CTA 0 + arrives ----
    if (lid == 0) {
        int slot = (int)rank * NWARP + wid;
        uint32_t lp = smem_u32(&part[slot][0]);
        uint32_t rp, rm;
        asm("mapa.shared::cluster.u32 %0, %1, %2;" : "=r"(rp) : "r"(lp), "r"(0));
        asm("mapa.shared::cluster.u32 %0, %1, %2;" : "=r"(rm) : "r"(mb_local), "r"(0));
        asm volatile("st.shared::cluster.f32 [%0+0],  %1;" :: "r"(rp), "f"(s_w)   : "memory");
        asm volatile("st.shared::cluster.f32 [%0+4],  %1;" :: "r"(rp), "f"(s_e)   : "memory");
        asm volatile("st.shared::cluster.f32 [%0+8],  %1;" :: "r"(rp), "f"(s_ew)  : "memory");
        asm volatile("st.shared::cluster.f32 [%0+12], %1;" :: "r"(rp), "f"(s_e2)  : "memory");
        asm volatile("st.shared::cluster.f32 [%0+16], %1;" :: "r"(rp), "f"(s_e2w) : "memory");
        asm volatile("mbarrier.arrive.release.cluster.shared::cluster.b64 _, [%0];"
                     :: "r"(rm) : "memory");
    }

    // ---- only CTA 0 warp 0 finishes; everyone else exits ----
    if (rank != 0 || wid != 0) return;

    // wait for all 64 arrivals (phase parity 0, acquire at cluster scope)
    {
        uint32_t done;
        asm volatile(
            "{\n\t"
            ".reg .pred p;\n\t"
            "mbarrier.try_wait.parity.acquire.cluster.shared::cta.b64 p, [%1], %2;\n\t"
            "selp.b32 %0, 1, 0, p;\n\t"
            "}"
            : "=r"(done) : "r"(mb_local), "r"(0) : "memory");
        if (!done) {
            asm volatile(
                "{\n\t"
                ".reg .pred P1;\n\t"
                "WAIT_LOOP_%=:\n\t"
                "mbarrier.try_wait.parity.acquire.cluster.shared::cta.b64 P1, [%0], %1, 0x989680;\n\t"
                "@P1 bra.uni WAIT_DONE_%=;\n\t"
                "bra.uni WAIT_LOOP_%=;\n\t"
                "WAIT_DONE_%=:\n\t"
                "}"
                :: "r"(mb_local), "r"(0) : "memory");
        }
    }

    // reduce 64 slots: lane l takes slots l and l+32
    float v0, v1, v2, v3, v4;
    {
        const float* a = &part[lid][0];
        const float* b = &part[lid + 32][0];
        v0 = a[0] + b[0];
        v1 = a[1] + b[1];
        v2 = a[2] + b[2];
        v3 = a[3] + b[3];
        v4 = a[4] + b[4];
    }
    #pragma unroll
    for (int off = 16; off > 0; off >>= 1) {
        v0 += __shfl_down_sync(0xffffffffu, v0, off);
        v1 += __shfl_down_sync(0xffffffffu, v1, off);
        v2 += __shfl_down_sync(0xffffffffu, v2, off);
        v3 += __shfl_down_sync(0xffffffffu, v3, off);
        v4 += __shfl_down_sync(0xffffffffu, v4, off);
    }

    if (lid == 0) {
        float S_w = v0, S_e = v1, S_ew = v2, S_e2 = v3, S_e2w = v4;
        float fn = (float)n;

        // mse (no NaNs => masked sums equal unmasked sums)
        float mse = S_e2w / S_w;

        // pairwise contrastive collapses:
        // num = 0.5*(n*Σe²w − 2*Σe*Σew + Σw*Σe²), den = 0.5*(n−1)*Σw
        float num = 0.5f * (fn * S_e2w - 2.0f * S_e * S_ew + S_w * S_e2);
        float den = 0.5f * (fn - 1.0f) * S_w;
        float c = num / den;

        // scale branch: c*(mse/c) == mse when taken
        bool do_scale = (c > EPSF) && (mse > EPSF) && (c < mse);
        float cs = do_scale ? mse : c;

        out[0] = 0.5f * (mse + cs);
    }
}

extern "C" void kernel_launch(void* const* d_in, const int* in_sizes, int n_in,
                              void* d_out, int out_size) {
    const float* x = (const float*)d_in[0];
    const float* t = (const float*)d_in[1];
    float* out = (float*)d_out;
    int n = in_sizes[0];
    lamse_kernel<<<NBLK, NTHR>>>(x, t, out, n);
}

// round 5
// speedup vs baseline: 1.0884x; 1.0884x over previous
#include <cuda_runtime.h>
#include <math.h>
#include <stdint.h>

#define REF_Y 0.5f
#define EPSF  1e-08f

#define NBLK  8                 // one cluster of 8 CTAs
#define NTHR  256               // 8 warps/CTA; 2048 threads -> exactly 1 float4/thread
#define NWARP (NTHR / 32)       // 8
#define NLEAD (NBLK * NWARP)    // 64 warp leaders cluster-wide

__device__ __forceinline__ uint32_t smem_u32(const void* p) {
    uint32_t a;
    asm("{ .reg .u64 t; cvta.to.shared.u64 t, %1; cvt.u32.u64 %0, t; }"
        : "=r"(a) : "l"(p));
    return a;
}

__global__ __launch_bounds__(NTHR, 1) __cluster_dims__(NBLK, 1, 1)
void lamse_kernel(const float* __restrict__ x,
                  const float* __restrict__ t,
                  float* __restrict__ out,
                  int n) {
    // landing zone (used in CTA 0's SMEM): 64 leader slots x 8 floats (5 used)
    __shared__ float part[NLEAD][8];

    const int tid = threadIdx.x;
    const int wid = tid >> 5;
    const int lid = tid & 31;
    uint32_t rank;
    asm("mov.u32 %0, %%cluster_ctarank;" : "=r"(rank));

    const int n4     = n >> 2;
    const int stride = NBLK * NTHR;
    const int gt     = (int)rank * NTHR + tid;

    const float4* __restrict__ x4 = (const float4*)x;
    const float4* __restrict__ t4 = (const float4*)t;

    // ---- per-thread accumulation (5 sums; inputs are NaN-free normals) ----
    float s_w = 0.f, s_e = 0.f, s_ew = 0.f, s_e2 = 0.f, s_e2w = 0.f;

    #define PROC(xj, tj) do {                                            \
        float _w = __fdividef(fabsf(REF_Y - (tj)),                       \
                              fabsf(REF_Y) + fabsf(tj) + EPSF);          \
        _w = fminf(fmaxf(_w, 0.1f), 2.0f);                               \
        float _e = (xj) - (tj);                                          \
        s_w  += _w;                                                      \
        s_e  += _e;                                                      \
        s_ew  = fmaf(_e, _w, s_ew);                                      \
        s_e2  = fmaf(_e, _e, s_e2);                                      \
        s_e2w = fmaf(_e * _e, _w, s_e2w);                                \
    } while (0)

    for (int i = gt; i < n4; i += stride) {
        float4 a = x4[i], b = t4[i];
        PROC(a.x, b.x); PROC(a.y, b.y); PROC(a.z, b.z); PROC(a.w, b.w);
    }
    for (int i = (n4 << 2) + gt; i < n; i += stride) {
        float xj = x[i], tj = t[i];
        PROC(xj, tj);
    }
    #undef PROC

    // ---- warp shuffle reduce (5 sums) ----
    #pragma unroll
    for (int off = 16; off > 0; off >>= 1) {
        s_w   += __shfl_down_sync(0xffffffffu, s_w,   off);
        s_e   += __shfl_down_sync(0xffffffffu, s_e,   off);
        s_ew  += __shfl_down_sync(0xffffffffu, s_ew,  off);
        s_e2  += __shfl_down_sync(0xffffffffu, s_e2,  off);
        s_e2w += __shfl_down_sync(0xffffffffu, s_e2w, off);
    }

    // ---- every warp leader DSMEM-stores its 5 partials into CTA 0 ----
    if (lid == 0) {
        int slot = (int)rank * NWARP + wid;
        uint32_t lp = smem_u32(&part[slot][0]);
        uint32_t rp;
        asm("mapa.shared::cluster.u32 %0, %1, %2;" : "=r"(rp) : "r"(lp), "r"(0));
        asm volatile("st.shared::cluster.f32 [%0+0],  %1;" :: "r"(rp), "f"(s_w)   : "memory");
        asm volatile("st.shared::cluster.f32 [%0+4],  %1;" :: "r"(rp), "f"(s_e)   : "memory");
        asm volatile("st.shared::cluster.f32 [%0+8],  %1;" :: "r"(rp), "f"(s_ew)  : "memory");
        asm volatile("st.shared::cluster.f32 [%0+12], %1;" :: "r"(rp), "f"(s_e2)  : "memory");
        asm volatile("st.shared::cluster.f32 [%0+16], %1;" :: "r"(rp), "f"(s_e2w) : "memory");
    }

    // ---- single cluster barrier: arrive=release (orders DSMEM stores),
    //      wait=acquire ----
    asm volatile("barrier.cluster.arrive.aligned;" ::: "memory");
    asm volatile("barrier.cluster.wait.aligned;"   ::: "memory");

    // ---- CTA 0 warp 0 reduces the 64 slots and finalizes ----
    if (rank == 0 && wid == 0) {
        float v0, v1, v2, v3, v4;
        {
            const float* a = &part[lid][0];
            const float* b = &part[lid + 32][0];
            v0 = a[0] + b[0];
            v1 = a[1] + b[1];
            v2 = a[2] + b[2];
            v3 = a[3] + b[3];
            v4 = a[4] + b[4];
        }
        #pragma unroll
        for (int off = 16; off > 0; off >>= 1) {
            v0 += __shfl_down_sync(0xffffffffu, v0, off);
            v1 += __shfl_down_sync(0xffffffffu, v1, off);
            v2 += __shfl_down_sync(0xffffffffu, v2, off);
            v3 += __shfl_down_sync(0xffffffffu, v3, off);
            v4 += __shfl_down_sync(0xffffffffu, v4, off);
        }
        if (lid == 0) {
            float S_w = v0, S_e = v1, S_ew = v2, S_e2 = v3, S_e2w = v4;
            float fn = (float)n;

            // mse (no NaNs => masked sums equal unmasked sums)
            float mse = S_e2w / S_w;

            // pairwise contrastive collapses to O(1):
            // num = 0.5*(n*Σe²w − 2*Σe*Σew + Σw*Σe²), den = 0.5*(n−1)*Σw
            float num = 0.5f * (fn * S_e2w - 2.0f * S_e * S_ew + S_w * S_e2);
            float den = 0.5f * (fn - 1.0f) * S_w;
            float c = num / den;

            // scale branch: c*(mse/c) == mse when taken
            bool do_scale = (c > EPSF) && (mse > EPSF) && (c < mse);
            float cs = do_scale ? mse : c;

            out[0] = 0.5f * (mse + cs);
        }
    }
}

extern "C" void kernel_launch(void* const* d_in, const int* in_sizes, int n_in,
                              void* d_out, int out_size) {
    const float* x = (const float*)d_in[0];
    const float* t = (const float*)d_in[1];
    float* out = (float*)d_out;
    int n = in_sizes[0];
    lamse_kernel<<<NBLK, NTHR>>>(x, t, out, n);
}